// round 8
// baseline (speedup 1.0000x reference)
// R8: attention q-tile 128 (halve K/V traffic per work unit); fused weight
// convert; launch order puts attn at #4 / gemm_out at #5 for ncu capture.
#include <cuda_runtime.h>
#include <cuda_bf16.h>
#include <math.h>
#include <stdint.h>

#define B_  4
#define S_  2048
#define D_  1024
#define H_  16
#define DK_ 64
#define M_  (B_ * S_)

// ---------------------------------------------------------------------------
// Scratch
// ---------------------------------------------------------------------------
__device__ __nv_bfloat16 g_xhi [M_ * D_];
__device__ __nv_bfloat16 g_xlo [M_ * D_];
__device__ __nv_bfloat16 g_qhi [M_ * D_];
__device__ __nv_bfloat16 g_qlo [M_ * D_];
__device__ __nv_bfloat16 g_khi [M_ * D_];
__device__ __nv_bfloat16 g_klo [M_ * D_];
__device__ __nv_bfloat16 g_vhi [M_ * D_];
__device__ __nv_bfloat16 g_vlo [M_ * D_];
__device__ __nv_bfloat16 g_aohi[M_ * D_];
__device__ __nv_bfloat16 g_aolo[M_ * D_];
__device__ __nv_bfloat16 g_whi [4][D_ * D_];
__device__ __nv_bfloat16 g_wlo [4][D_ * D_];

// ---------------------------------------------------------------------------
// PTX helpers
// ---------------------------------------------------------------------------
__device__ __forceinline__ uint32_t smem_u32(const void* p) {
    uint32_t a;
    asm("{ .reg .u64 t; cvta.to.shared.u64 t, %1; cvt.u32.u64 %0, t; }" : "=r"(a) : "l"(p));
    return a;
}

#define CP_ASYNC_16(sa, gp) \
    asm volatile("cp.async.cg.shared.global [%0], [%1], 16;" :: "r"(sa), "l"(gp))
#define CP_COMMIT() asm volatile("cp.async.commit_group;" ::: "memory")
template<int N> __device__ __forceinline__ void cp_wait() {
    asm volatile("cp.async.wait_group %0;" :: "n"(N) : "memory");
}

__device__ __forceinline__ void mma16816(float* d, const uint32_t* a, const uint32_t* b) {
    asm volatile("mma.sync.aligned.m16n8k16.row.col.f32.bf16.bf16.f32 "
                 "{%0,%1,%2,%3}, {%4,%5,%6,%7}, {%8,%9}, {%0,%1,%2,%3};"
                 : "+f"(d[0]), "+f"(d[1]), "+f"(d[2]), "+f"(d[3])
                 : "r"(a[0]), "r"(a[1]), "r"(a[2]), "r"(a[3]), "r"(b[0]), "r"(b[1]));
}

// fp32 pair -> bf16x2 hi + exact residual bf16x2 lo. a = even col, b = odd col.
__device__ __forceinline__ void pack_hilo(float a, float b, uint32_t& hi, uint32_t& lo) {
    uint32_t h;
    asm("cvt.rn.bf16x2.f32 %0, %1, %2;" : "=r"(h) : "f"(b), "f"(a));
    float ra = a - __uint_as_float(h << 16);
    float rb = b - __uint_as_float(h & 0xffff0000u);
    uint32_t l;
    asm("cvt.rn.bf16x2.f32 %0, %1, %2;" : "=r"(l) : "f"(rb), "f"(ra));
    hi = h; lo = l;
}

// ----- 64B-row tiles (GEMM, BK=32) -----
__device__ __forceinline__ uint32_t sw_off(int row, int chunk) {
    return (uint32_t)(row * 64 + ((chunk ^ ((row >> 1) & 3)) << 4));
}
__device__ __forceinline__ void ldm_a(uint32_t tile, int row0, int kstep, int lane, uint32_t* r) {
    int row = row0 + (lane & 15);
    int ck  = kstep * 2 + ((lane >> 4) & 1);
    uint32_t addr = tile + sw_off(row, ck);
    asm volatile("ldmatrix.sync.aligned.m8n8.x4.shared.b16 {%0,%1,%2,%3}, [%4];"
                 : "=r"(r[0]), "=r"(r[1]), "=r"(r[2]), "=r"(r[3]) : "r"(addr));
}
__device__ __forceinline__ void ldm_b(uint32_t tile, int row0, int kstep, int lane, uint32_t* r) {
    int row = row0 + (lane & 7) + ((lane & 16) ? 8 : 0);
    int ck  = kstep * 2 + ((lane >> 3) & 1);
    uint32_t addr = tile + sw_off(row, ck);
    asm volatile("ldmatrix.sync.aligned.m8n8.x4.shared.b16 {%0,%1,%2,%3}, [%4];"
                 : "=r"(r[0]), "=r"(r[1]), "=r"(r[2]), "=r"(r[3]) : "r"(addr));
}

// ----- 128B-row tiles (attention) -----
__device__ __forceinline__ uint32_t swoff128(int row, int ck) {
    return (uint32_t)(row * 128 + ((ck ^ (row & 7)) << 4));
}
__device__ __forceinline__ void ldm_a128(uint32_t tile, int row0, int t4, int lane, uint32_t* r) {
    int row = row0 + (lane & 15);
    int ck  = t4 * 2 + ((lane >> 4) & 1);
    uint32_t addr = tile + swoff128(row, ck);
    asm volatile("ldmatrix.sync.aligned.m8n8.x4.shared.b16 {%0,%1,%2,%3}, [%4];"
                 : "=r"(r[0]), "=r"(r[1]), "=r"(r[2]), "=r"(r[3]) : "r"(addr));
}
__device__ __forceinline__ void ldm_b128(uint32_t tile, int n0, int t4, int lane, uint32_t* r) {
    int row = n0 + (lane & 7) + ((lane >> 1) & 8);
    int ck  = t4 * 2 + ((lane >> 3) & 1);
    uint32_t addr = tile + swoff128(row, ck);
    asm volatile("ldmatrix.sync.aligned.m8n8.x4.shared.b16 {%0,%1,%2,%3}, [%4];"
                 : "=r"(r[0]), "=r"(r[1]), "=r"(r[2]), "=r"(r[3]) : "r"(addr));
}
__device__ __forceinline__ void ldm_vt128(uint32_t tile, int k0, int jp, int lane, uint32_t* r) {
    int row = k0 + (lane & 7) + (lane & 8);
    int ck  = jp * 2 + ((lane >> 4) & 1);
    uint32_t addr = tile + swoff128(row, ck);
    asm volatile("ldmatrix.sync.aligned.m8n8.x4.trans.shared.b16 {%0,%1,%2,%3}, [%4];"
                 : "=r"(r[0]), "=r"(r[1]), "=r"(r[2]), "=r"(r[3]) : "r"(addr));
}

// ---------------------------------------------------------------------------
// converts
// ---------------------------------------------------------------------------
__global__ __launch_bounds__(256) void f32_to_hilo(const float* __restrict__ in,
                                                   __nv_bfloat16* __restrict__ hi,
                                                   __nv_bfloat16* __restrict__ lo,
                                                   int n2)
{
    int i = blockIdx.x * blockDim.x + threadIdx.x;
    if (i >= n2) return;
    float2 v = ((const float2*)in)[i];
    uint32_t h, l;
    pack_hilo(v.x, v.y, h, l);
    ((uint32_t*)hi)[i] = h;
    ((uint32_t*)lo)[i] = l;
}

// all four weights in ONE launch (blockIdx.y selects tensor)
__global__ __launch_bounds__(256) void w4_to_hilo(const float* __restrict__ w0,
                                                  const float* __restrict__ w1,
                                                  const float* __restrict__ w2,
                                                  const float* __restrict__ w3,
                                                  __nv_bfloat16* __restrict__ hi,
                                                  __nv_bfloat16* __restrict__ lo)
{
    const int n2 = D_ * D_ / 2;
    int i = blockIdx.x * blockDim.x + threadIdx.x;
    if (i >= n2) return;
    const int which = blockIdx.y;
    const float* src = (which == 0) ? w0 : (which == 1) ? w1 : (which == 2) ? w2 : w3;
    float2 v = ((const float2*)src)[i];
    uint32_t h, l;
    pack_hilo(v.x, v.y, h, l);
    ((uint32_t*)(hi + (size_t)which * (D_ * D_)))[i] = h;
    ((uint32_t*)(lo + (size_t)which * (D_ * D_)))[i] = l;
}

// ---------------------------------------------------------------------------
// Shared GEMM mainloop (bf16x3, NT, CTA 128x128, BK=32, double-buffered)
// ---------------------------------------------------------------------------
#define STAGE_B   32768
#define GEMM_SMEM (2 * STAGE_B)
#define NCHUNK    32

__device__ __forceinline__ void gemm_mainloop(
    const __nv_bfloat16* __restrict__ Ahi, const __nv_bfloat16* __restrict__ Alo,
    const __nv_bfloat16* __restrict__ Bhi, const __nv_bfloat16* __restrict__ Blo,
    uint32_t sb, int bm, int bn, int t, int lane, int wm, int wn,
    float d[4][4][4])
{
    const int r0 = t >> 2,         c0 = t & 3;
    const int r1 = (t + 256) >> 2, c1 = t & 3;

    auto load_chunk = [&](int chunk, int st) {
        const size_t kb = (size_t)chunk * 32;
        const uint32_t s = sb + (uint32_t)st * STAGE_B;
        {
            uint32_t so = sw_off(r0, c0);
            const size_t ga = (size_t)(bm + r0) * D_ + kb + c0 * 8;
            const size_t gb = (size_t)(bn + r0) * D_ + kb + c0 * 8;
            CP_ASYNC_16(s + so,         Ahi + ga);
            CP_ASYNC_16(s + 8192  + so, Alo + ga);
            CP_ASYNC_16(s + 16384 + so, Bhi + gb);
            CP_ASYNC_16(s + 24576 + so, Blo + gb);
        }
        {
            uint32_t so = sw_off(r1, c1);
            const size_t ga = (size_t)(bm + r1) * D_ + kb + c1 * 8;
            const size_t gb = (size_t)(bn + r1) * D_ + kb + c1 * 8;
            CP_ASYNC_16(s + so,         Ahi + ga);
            CP_ASYNC_16(s + 8192  + so, Alo + ga);
            CP_ASYNC_16(s + 16384 + so, Bhi + gb);
            CP_ASYNC_16(s + 24576 + so, Blo + gb);
        }
        CP_COMMIT();
    };

    load_chunk(0, 0);

    for (int chunk = 0; chunk < NCHUNK; chunk++) {
        const int st = chunk & 1;
        if (chunk + 1 < NCHUNK) { load_chunk(chunk + 1, st ^ 1); cp_wait<1>(); }
        else                    { cp_wait<0>(); }
        __syncthreads();

        const uint32_t tAh = sb + (uint32_t)st * STAGE_B;
        const uint32_t tAl = tAh + 8192;
        const uint32_t tBh = tAh + 16384;
        const uint32_t tBl = tAh + 24576;

#pragma unroll
        for (int ks = 0; ks < 2; ks++) {
            uint32_t ah[4][4], al[4][4];
#pragma unroll
            for (int i = 0; i < 4; i++) {
                ldm_a(tAh, wm + i * 16, ks, lane, ah[i]);
                ldm_a(tAl, wm + i * 16, ks, lane, al[i]);
            }
            uint32_t bh[2][4], bl[2][4];
#pragma unroll
            for (int jp = 0; jp < 2; jp++) {
                ldm_b(tBh, wn + jp * 16, ks, lane, bh[jp]);
                ldm_b(tBl, wn + jp * 16, ks, lane, bl[jp]);
            }
#pragma unroll
            for (int i = 0; i < 4; i++)
#pragma unroll
                for (int j = 0; j < 4; j++) {
                    const uint32_t* ph = &bh[j >> 1][(j & 1) * 2];
                    const uint32_t* pl = &bl[j >> 1][(j & 1) * 2];
                    mma16816(d[i][j], ah[i], ph);
                    mma16816(d[i][j], ah[i], pl);
                    mma16816(d[i][j], al[i], ph);
                }
        }
        __syncthreads();
    }
}

// ---------------------------------------------------------------------------
// Fused QKV projection
// ---------------------------------------------------------------------------
__global__ __launch_bounds__(256) void gemm_qkv(
    const __nv_bfloat16* __restrict__ Ahi, const __nv_bfloat16* __restrict__ Alo,
    const __nv_bfloat16* __restrict__ Whi, const __nv_bfloat16* __restrict__ Wlo,
    __nv_bfloat16* __restrict__ Qhi, __nv_bfloat16* __restrict__ Qlo,
    __nv_bfloat16* __restrict__ Khi, __nv_bfloat16* __restrict__ Klo,
    __nv_bfloat16* __restrict__ Vhi, __nv_bfloat16* __restrict__ Vlo)
{
    extern __shared__ __align__(1024) char smem[];
    const uint32_t sb = smem_u32(smem);

    const int t     = threadIdx.x;
    const int lane  = t & 31;
    const int w     = t >> 5;
    const int wm    = (w >> 2) * 64;
    const int wn    = (w & 3) * 32;
    const int which = blockIdx.x >> 3;
    const int bn    = (blockIdx.x & 7) * 128;
    const int bm    = blockIdx.y * 128;

    const __nv_bfloat16* Bhi = Whi + (size_t)which * (D_ * D_);
    const __nv_bfloat16* Blo = Wlo + (size_t)which * (D_ * D_);
    __nv_bfloat16* Chi = (which == 0) ? Qhi : (which == 1) ? Khi : Vhi;
    __nv_bfloat16* Clo = (which == 0) ? Qlo : (which == 1) ? Klo : Vlo;
    const float scale = (which == 0) ? 0.125f : 1.0f;

    float d[4][4][4];
#pragma unroll
    for (int i = 0; i < 4; i++)
#pragma unroll
        for (int j = 0; j < 4; j++)
#pragma unroll
            for (int e = 0; e < 4; e++) d[i][j][e] = 0.0f;

    gemm_mainloop(Ahi, Alo, Bhi, Blo, sb, bm, bn, t, lane, wm, wn, d);

#pragma unroll
    for (int i = 0; i < 4; i++) {
        const int row = bm + wm + i * 16 + (lane >> 2);
#pragma unroll
        for (int j = 0; j < 4; j++) {
            const int col = bn + wn + j * 8 + (lane & 3) * 2;
            uint32_t h01, l01, h23, l23;
            pack_hilo(d[i][j][0] * scale, d[i][j][1] * scale, h01, l01);
            pack_hilo(d[i][j][2] * scale, d[i][j][3] * scale, h23, l23);
            *(uint32_t*)(Chi + (size_t)row * D_ + col)       = h01;
            *(uint32_t*)(Clo + (size_t)row * D_ + col)       = l01;
            *(uint32_t*)(Chi + (size_t)(row + 8) * D_ + col) = h23;
            *(uint32_t*)(Clo + (size_t)(row + 8) * D_ + col) = l23;
        }
    }
}

// ---------------------------------------------------------------------------
// O-projection GEMM (fp32 output)
// ---------------------------------------------------------------------------
__global__ __launch_bounds__(256) void gemm_out(
    const __nv_bfloat16* __restrict__ Ahi, const __nv_bfloat16* __restrict__ Alo,
    const __nv_bfloat16* __restrict__ Bhi, const __nv_bfloat16* __restrict__ Blo,
    float* __restrict__ C)
{
    extern __shared__ __align__(1024) char smem[];
    const uint32_t sb = smem_u32(smem);

    const int t    = threadIdx.x;
    const int lane = t & 31;
    const int w    = t >> 5;
    const int wm   = (w >> 2) * 64;
    const int wn   = (w & 3) * 32;
    const int bm   = blockIdx.y * 128;
    const int bn   = blockIdx.x * 128;

    float d[4][4][4];
#pragma unroll
    for (int i = 0; i < 4; i++)
#pragma unroll
        for (int j = 0; j < 4; j++)
#pragma unroll
            for (int e = 0; e < 4; e++) d[i][j][e] = 0.0f;

    gemm_mainloop(Ahi, Alo, Bhi, Blo, sb, bm, bn, t, lane, wm, wn, d);

#pragma unroll
    for (int i = 0; i < 4; i++) {
        const int row = bm + wm + i * 16 + (lane >> 2);
#pragma unroll
        for (int j = 0; j < 4; j++) {
            const int col = bn + wn + j * 8 + (lane & 3) * 2;
            *(float2*)(C + (size_t)row * D_ + col)       = make_float2(d[i][j][0], d[i][j][1]);
            *(float2*)(C + (size_t)(row + 8) * D_ + col) = make_float2(d[i][j][2], d[i][j][3]);
        }
    }
}

// ---------------------------------------------------------------------------
// Flash attention, q-tile = 128 rows, 256 threads (8 warps x 16 q-rows).
// Smem: Qhi[16K] Qlo[16K] + 2 stages of {Khi,Klo,Vhi,Vlo} (32K each) = 96KB.
// K tiles remain 64 keys; ktiles per CTA = 2*qt+2, last two masked.
// ---------------------------------------------------------------------------
#define ATT_SMEM 98304

__global__ __launch_bounds__(256) void attn_mma(
    const __nv_bfloat16* __restrict__ Qhi, const __nv_bfloat16* __restrict__ Qlo,
    const __nv_bfloat16* __restrict__ Khi, const __nv_bfloat16* __restrict__ Klo,
    const __nv_bfloat16* __restrict__ Vhi, const __nv_bfloat16* __restrict__ Vlo,
    __nv_bfloat16* __restrict__ AOhi, __nv_bfloat16* __restrict__ AOlo)
{
    extern __shared__ __align__(1024) char smem[];
    const uint32_t sb = smem_u32(smem);
    const int qt   = (int)gridDim.x - 1 - (int)blockIdx.x;  // biggest first
    const int h    = blockIdx.y;
    const int b    = blockIdx.z;
    const int tid  = threadIdx.x;
    const int lane = tid & 31;
    const int w    = tid >> 5;

    const size_t rowbase = (size_t)b * S_;
    const size_t cb      = (size_t)h * DK_;
    const int    q0      = qt * 128;

    const uint32_t sQh = sb, sQl = sb + 16384;

    // Q tiles: 128 rows x 8 chunks, hi+lo
#pragma unroll
    for (int i = 0; i < 4; i++) {
        int p = tid + 256 * i; int r = p >> 3, ck = p & 7;
        size_t g = (rowbase + q0 + r) * D_ + cb + ck * 8;
        uint32_t so = swoff128(r, ck);
        CP_ASYNC_16(sQh + so, Qhi + g);
        CP_ASYNC_16(sQl + so, Qlo + g);
    }
    CP_COMMIT();

    auto load_kv = [&](int kt, int st) {
        uint32_t s = sb + 32768 + (uint32_t)st * 32768;
#pragma unroll
        for (int i = 0; i < 2; i++) {
            int p = tid + 256 * i; int r = p >> 3, ck = p & 7;
            uint32_t so = swoff128(r, ck);
            size_t g = (rowbase + kt * 64 + r) * D_ + cb + ck * 8;
            CP_ASYNC_16(s + so,         Khi + g);
            CP_ASYNC_16(s + 8192  + so, Klo + g);
            CP_ASYNC_16(s + 16384 + so, Vhi + g);
            CP_ASYNC_16(s + 24576 + so, Vlo + g);
        }
        CP_COMMIT();
    };
    load_kv(0, 0);

    cp_wait<1>();
    __syncthreads();

    uint32_t qh[4][4], ql[4][4];
#pragma unroll
    for (int t4 = 0; t4 < 4; t4++) {
        ldm_a128(sQh, w * 16, t4, lane, qh[t4]);
        ldm_a128(sQl, w * 16, t4, lane, ql[t4]);
    }

    float o[8][4];
#pragma unroll
    for (int j = 0; j < 8; j++)
#pragma unroll
        for (int e = 0; e < 4; e++) o[j][e] = 0.0f;
    float miA = -INFINITY, miB = -INFINITY, liA = 0.0f, liB = 0.0f;

    const int rA  = w * 16 + (lane >> 2);
    const int cl  = 2 * (lane & 3);
    const int grA = q0 + rA;                 // global q row (A); B = grA+8
    const int nkt = 2 * qt + 2;

    for (int kt = 0; kt < nkt; kt++) {
        const int st = kt & 1;
        if (kt + 1 < nkt) { load_kv(kt + 1, st ^ 1); cp_wait<1>(); }
        else              { cp_wait<0>(); }
        __syncthreads();

        const uint32_t Kh = sb + 32768 + (uint32_t)st * 32768;
        const uint32_t Kl = Kh + 8192, Vh = Kh + 16384, Vl = Kh + 24576;

        float s[8][4];
#pragma unroll
        for (int j = 0; j < 8; j++)
#pragma unroll
            for (int e = 0; e < 4; e++) s[j][e] = 0.0f;

#pragma unroll
        for (int t4 = 0; t4 < 4; t4++) {
#pragma unroll
            for (int jp = 0; jp < 4; jp++) {
                uint32_t kh[4], kl[4];
                ldm_b128(Kh, jp * 16, t4, lane, kh);
                ldm_b128(Kl, jp * 16, t4, lane, kl);
                mma16816(s[2 * jp],     qh[t4], kh);
                mma16816(s[2 * jp],     qh[t4], kl);
                mma16816(s[2 * jp],     ql[t4], kh);
                mma16816(s[2 * jp + 1], qh[t4], kh + 2);
                mma16816(s[2 * jp + 1], qh[t4], kl + 2);
                mma16816(s[2 * jp + 1], ql[t4], kh + 2);
            }
        }

        // causal mask: only the last two ktiles can cross the diagonal
        if (kt >= nkt - 2) {
#pragma unroll
            for (int j = 0; j < 8; j++) {
                int c = kt * 64 + 8 * j + cl;    // global key col
                if (c     > grA)     s[j][0] = -INFINITY;
                if (c + 1 > grA)     s[j][1] = -INFINITY;
                if (c     > grA + 8) s[j][2] = -INFINITY;
                if (c + 1 > grA + 8) s[j][3] = -INFINITY;
            }
        }

        float mxA = s[0][0], mxB = s[0][2];
#pragma unroll
        for (int j = 0; j < 8; j++) {
            mxA = fmaxf(mxA, fmaxf(s[j][0], s[j][1]));
            mxB = fmaxf(mxB, fmaxf(s[j][2], s[j][3]));
        }
        mxA = fmaxf(mxA, __shfl_xor_sync(0xffffffffu, mxA, 1));
        mxA = fmaxf(mxA, __shfl_xor_sync(0xffffffffu, mxA, 2));
        mxB = fmaxf(mxB, __shfl_xor_sync(0xffffffffu, mxB, 1));
        mxB = fmaxf(mxB, __shfl_xor_sync(0xffffffffu, mxB, 2));

        float nA = fmaxf(miA, mxA), nB = fmaxf(miB, mxB);
        float aA = __expf(miA - nA), aB = __expf(miB - nB);
        miA = nA; miB = nB;
        liA *= aA; liB *= aB;
#pragma unroll
        for (int j = 0; j < 8; j++) {
            s[j][0] = __expf(s[j][0] - miA);
            s[j][1] = __expf(s[j][1] - miA);
            s[j][2] = __expf(s[j][2] - miB);
            s[j][3] = __expf(s[j][3] - miB);
            liA += s[j][0] + s[j][1];
            liB += s[j][2] + s[j][3];
            o[j][0] *= aA; o[j][1] *= aA; o[j][2] *= aB; o[j][3] *= aB;
        }

        uint32_t ph[4][4], pl[4][4];
#pragma unroll
        for (int t4 = 0; t4 < 4; t4++) {
            pack_hilo(s[2 * t4][0],     s[2 * t4][1],     ph[t4][0], pl[t4][0]);
            pack_hilo(s[2 * t4][2],     s[2 * t4][3],     ph[t4][1], pl[t4][1]);
            pack_hilo(s[2 * t4 + 1][0], s[2 * t4 + 1][1], ph[t4][2], pl[t4][2]);
            pack_hilo(s[2 * t4 + 1][2], s[2 * t4 + 1][3], ph[t4][3], pl[t4][3]);
        }

#pragma unroll
        for (int t4 = 0; t4 < 4; t4++) {
#pragma unroll
            for (int jp = 0; jp < 4; jp++) {
                uint32_t vh[4], vl[4];
                ldm_vt128(Vh, t4 * 16, jp, lane, vh);
                ldm_vt128(Vl, t4 * 16, jp, lane, vl);
                mma16816(o[2 * jp],     ph[t4], vh);
                mma16816(o[2 * jp],     pl[t4], vh);
                mma16816(o[2 * jp],     ph[t4], vl);
                mma16816(o[2 * jp + 1], ph[t4], vh + 2);
                mma16816(o[2 * jp + 1], pl[t4], vh + 2);
                mma16816(o[2 * jp + 1], ph[t4], vl + 2);
            }
        }
        __syncthreads();
    }

    liA += __shfl_xor_sync(0xffffffffu, liA, 1);
    liA += __shfl_xor_sync(0xffffffffu, liA, 2);
    liB += __shfl_xor_sync(0xffffffffu, liB, 1);
    liB += __shfl_xor_sync(0xffffffffu, liB, 2);
    const float invA = 1.0f / liA, invB = 1.0f / liB;

    const size_t gA = (rowbase + q0 + rA) * D_ + cb + cl;
#pragma unroll
    for (int j = 0; j < 8; j++) {
        uint32_t hA, lA, hB, lB;
        pack_hilo(o[j][0] * invA, o[j][1] * invA, hA, lA);
        pack_hilo(o[j][2] * invB, o[j][3] * invB, hB, lB);
        *(uint32_t*)(AOhi + gA + 8 * j)           = hA;
        *(uint32_t*)(AOlo + gA + 8 * j)           = lA;
        *(uint32_t*)(AOhi + gA + 8 * j + 8 * D_)  = hB;
        *(uint32_t*)(AOlo + gA + 8 * j + 8 * D_)  = lB;
    }
}

// ---------------------------------------------------------------------------
// kernel_launch
// ---------------------------------------------------------------------------
extern "C" void kernel_launch(void* const* d_in, const int* in_sizes, int n_in,
                              void* d_out, int out_size)
{
    const float* x  = (const float*)d_in[0];
    const float* wp[4] = { (const float*)d_in[1], (const float*)d_in[2],
                           (const float*)d_in[3], (const float*)d_in[4] };
    float* out = (float*)d_out;

    __nv_bfloat16 *xhi, *xlo, *qhi, *qlo, *khi, *klo, *vhi, *vlo, *aohi, *aolo, *whi, *wlo;
    cudaGetSymbolAddress((void**)&xhi,  g_xhi);
    cudaGetSymbolAddress((void**)&xlo,  g_xlo);
    cudaGetSymbolAddress((void**)&qhi,  g_qhi);
    cudaGetSymbolAddress((void**)&qlo,  g_qlo);
    cudaGetSymbolAddress((void**)&khi,  g_khi);
    cudaGetSymbolAddress((void**)&klo,  g_klo);
    cudaGetSymbolAddress((void**)&vhi,  g_vhi);
    cudaGetSymbolAddress((void**)&vlo,  g_vlo);
    cudaGetSymbolAddress((void**)&aohi, g_aohi);
    cudaGetSymbolAddress((void**)&aolo, g_aolo);
    cudaGetSymbolAddress((void**)&whi,  g_whi);
    cudaGetSymbolAddress((void**)&wlo,  g_wlo);

    const int n2x = M_ * D_ / 2;
    const int n2w = D_ * D_ / 2;
    // launch order fixed: 1:x-convert 2:w-convert 3:gemm_qkv 4:attn 5:gemm_out
    f32_to_hilo<<<(n2x + 255) / 256, 256>>>(x, xhi, xlo, n2x);
    w4_to_hilo<<<dim3((n2w + 255) / 256, 4), 256>>>(wp[0], wp[1], wp[2], wp[3], whi, wlo);

    cudaFuncSetAttribute(gemm_qkv, cudaFuncAttributeMaxDynamicSharedMemorySize, GEMM_SMEM);
    cudaFuncSetAttribute(gemm_out, cudaFuncAttributeMaxDynamicSharedMemorySize, GEMM_SMEM);
    cudaFuncSetAttribute(attn_mma, cudaFuncAttributeMaxDynamicSharedMemorySize, ATT_SMEM);

    gemm_qkv<<<dim3(24, M_ / 128), 256, GEMM_SMEM>>>(xhi, xlo, whi, wlo,
                                                     qhi, qlo, khi, klo, vhi, vlo);

    attn_mma<<<dim3(S_ / 128, H_, B_), 256, ATT_SMEM>>>(qhi, qlo, khi, klo, vhi, vlo, aohi, aolo);

    gemm_out<<<dim3(D_ / 128, M_ / 128), 256, GEMM_SMEM>>>(
        aohi, aolo, whi + 3 * (size_t)(D_ * D_), wlo + 3 * (size_t)(D_ * D_), out);
}

// round 9
// speedup vs baseline: 1.0568x; 1.0568x over previous
// R9: revert attn to q64/2-CTA-per-SM (R8 showed q128 lost softmax/MMA overlap,
// occ 12.4%); GEMM mainloop -> 3-stage cp.async, single barrier per chunk.
#include <cuda_runtime.h>
#include <cuda_bf16.h>
#include <math.h>
#include <stdint.h>

#define B_  4
#define S_  2048
#define D_  1024
#define H_  16
#define DK_ 64
#define M_  (B_ * S_)

// ---------------------------------------------------------------------------
// Scratch
// ---------------------------------------------------------------------------
__device__ __nv_bfloat16 g_xhi [M_ * D_];
__device__ __nv_bfloat16 g_xlo [M_ * D_];
__device__ __nv_bfloat16 g_qhi [M_ * D_];
__device__ __nv_bfloat16 g_qlo [M_ * D_];
__device__ __nv_bfloat16 g_khi [M_ * D_];
__device__ __nv_bfloat16 g_klo [M_ * D_];
__device__ __nv_bfloat16 g_vhi [M_ * D_];
__device__ __nv_bfloat16 g_vlo [M_ * D_];
__device__ __nv_bfloat16 g_aohi[M_ * D_];
__device__ __nv_bfloat16 g_aolo[M_ * D_];
__device__ __nv_bfloat16 g_whi [4][D_ * D_];
__device__ __nv_bfloat16 g_wlo [4][D_ * D_];

// ---------------------------------------------------------------------------
// PTX helpers
// ---------------------------------------------------------------------------
__device__ __forceinline__ uint32_t smem_u32(const void* p) {
    uint32_t a;
    asm("{ .reg .u64 t; cvta.to.shared.u64 t, %1; cvt.u32.u64 %0, t; }" : "=r"(a) : "l"(p));
    return a;
}

#define CP_ASYNC_16(sa, gp) \
    asm volatile("cp.async.cg.shared.global [%0], [%1], 16;" :: "r"(sa), "l"(gp))
#define CP_COMMIT() asm volatile("cp.async.commit_group;" ::: "memory")
template<int N> __device__ __forceinline__ void cp_wait() {
    asm volatile("cp.async.wait_group %0;" :: "n"(N) : "memory");
}

__device__ __forceinline__ void mma16816(float* d, const uint32_t* a, const uint32_t* b) {
    asm volatile("mma.sync.aligned.m16n8k16.row.col.f32.bf16.bf16.f32 "
                 "{%0,%1,%2,%3}, {%4,%5,%6,%7}, {%8,%9}, {%0,%1,%2,%3};"
                 : "+f"(d[0]), "+f"(d[1]), "+f"(d[2]), "+f"(d[3])
                 : "r"(a[0]), "r"(a[1]), "r"(a[2]), "r"(a[3]), "r"(b[0]), "r"(b[1]));
}

// fp32 pair -> bf16x2 hi + exact residual bf16x2 lo. a = even col, b = odd col.
__device__ __forceinline__ void pack_hilo(float a, float b, uint32_t& hi, uint32_t& lo) {
    uint32_t h;
    asm("cvt.rn.bf16x2.f32 %0, %1, %2;" : "=r"(h) : "f"(b), "f"(a));
    float ra = a - __uint_as_float(h << 16);
    float rb = b - __uint_as_float(h & 0xffff0000u);
    uint32_t l;
    asm("cvt.rn.bf16x2.f32 %0, %1, %2;" : "=r"(l) : "f"(rb), "f"(ra));
    hi = h; lo = l;
}

// ----- 64B-row tiles (GEMM, BK=32) -----
__device__ __forceinline__ uint32_t sw_off(int row, int chunk) {
    return (uint32_t)(row * 64 + ((chunk ^ ((row >> 1) & 3)) << 4));
}
__device__ __forceinline__ void ldm_a(uint32_t tile, int row0, int kstep, int lane, uint32_t* r) {
    int row = row0 + (lane & 15);
    int ck  = kstep * 2 + ((lane >> 4) & 1);
    uint32_t addr = tile + sw_off(row, ck);
    asm volatile("ldmatrix.sync.aligned.m8n8.x4.shared.b16 {%0,%1,%2,%3}, [%4];"
                 : "=r"(r[0]), "=r"(r[1]), "=r"(r[2]), "=r"(r[3]) : "r"(addr));
}
__device__ __forceinline__ void ldm_b(uint32_t tile, int row0, int kstep, int lane, uint32_t* r) {
    int row = row0 + (lane & 7) + ((lane & 16) ? 8 : 0);
    int ck  = kstep * 2 + ((lane >> 3) & 1);
    uint32_t addr = tile + sw_off(row, ck);
    asm volatile("ldmatrix.sync.aligned.m8n8.x4.shared.b16 {%0,%1,%2,%3}, [%4];"
                 : "=r"(r[0]), "=r"(r[1]), "=r"(r[2]), "=r"(r[3]) : "r"(addr));
}

// ----- 128B-row tiles (attention, 64x64 bf16) -----
__device__ __forceinline__ uint32_t swoff128(int row, int ck) {
    return (uint32_t)(row * 128 + ((ck ^ (row & 7)) << 4));
}
__device__ __forceinline__ void ldm_a128(uint32_t tile, int row0, int t4, int lane, uint32_t* r) {
    int row = row0 + (lane & 15);
    int ck  = t4 * 2 + ((lane >> 4) & 1);
    uint32_t addr = tile + swoff128(row, ck);
    asm volatile("ldmatrix.sync.aligned.m8n8.x4.shared.b16 {%0,%1,%2,%3}, [%4];"
                 : "=r"(r[0]), "=r"(r[1]), "=r"(r[2]), "=r"(r[3]) : "r"(addr));
}
__device__ __forceinline__ void ldm_b128(uint32_t tile, int n0, int t4, int lane, uint32_t* r) {
    int row = n0 + (lane & 7) + ((lane >> 1) & 8);
    int ck  = t4 * 2 + ((lane >> 3) & 1);
    uint32_t addr = tile + swoff128(row, ck);
    asm volatile("ldmatrix.sync.aligned.m8n8.x4.shared.b16 {%0,%1,%2,%3}, [%4];"
                 : "=r"(r[0]), "=r"(r[1]), "=r"(r[2]), "=r"(r[3]) : "r"(addr));
}
__device__ __forceinline__ void ldm_vt128(uint32_t tile, int k0, int jp, int lane, uint32_t* r) {
    int row = k0 + (lane & 7) + (lane & 8);
    int ck  = jp * 2 + ((lane >> 4) & 1);
    uint32_t addr = tile + swoff128(row, ck);
    asm volatile("ldmatrix.sync.aligned.m8n8.x4.trans.shared.b16 {%0,%1,%2,%3}, [%4];"
                 : "=r"(r[0]), "=r"(r[1]), "=r"(r[2]), "=r"(r[3]) : "r"(addr));
}

// ---------------------------------------------------------------------------
// converts
// ---------------------------------------------------------------------------
__global__ __launch_bounds__(256) void f32_to_hilo(const float* __restrict__ in,
                                                   __nv_bfloat16* __restrict__ hi,
                                                   __nv_bfloat16* __restrict__ lo,
                                                   int n2)
{
    int i = blockIdx.x * blockDim.x + threadIdx.x;
    if (i >= n2) return;
    float2 v = ((const float2*)in)[i];
    uint32_t h, l;
    pack_hilo(v.x, v.y, h, l);
    ((uint32_t*)hi)[i] = h;
    ((uint32_t*)lo)[i] = l;
}

__global__ __launch_bounds__(256) void w4_to_hilo(const float* __restrict__ w0,
                                                  const float* __restrict__ w1,
                                                  const float* __restrict__ w2,
                                                  const float* __restrict__ w3,
                                                  __nv_bfloat16* __restrict__ hi,
                                                  __nv_bfloat16* __restrict__ lo)
{
    const int n2 = D_ * D_ / 2;
    int i = blockIdx.x * blockDim.x + threadIdx.x;
    if (i >= n2) return;
    const int which = blockIdx.y;
    const float* src = (which == 0) ? w0 : (which == 1) ? w1 : (which == 2) ? w2 : w3;
    float2 v = ((const float2*)src)[i];
    uint32_t h, l;
    pack_hilo(v.x, v.y, h, l);
    ((uint32_t*)(hi + (size_t)which * (D_ * D_)))[i] = h;
    ((uint32_t*)(lo + (size_t)which * (D_ * D_)))[i] = l;
}

// ---------------------------------------------------------------------------
// Shared GEMM mainloop — 3-stage cp.async, ONE barrier per chunk.
// Stage s = chunk % 3 at sb + s*STAGE_B. Writes at iter k go to stage
// (k+2)%3 == (k-1)%3 whose readers finished before this iter's barrier.
// ---------------------------------------------------------------------------
#define STAGE_B   32768
#define GEMM_SMEM (3 * STAGE_B)
#define NCHUNK    32

__device__ __forceinline__ void gemm_mainloop(
    const __nv_bfloat16* __restrict__ Ahi, const __nv_bfloat16* __restrict__ Alo,
    const __nv_bfloat16* __restrict__ Bhi, const __nv_bfloat16* __restrict__ Blo,
    uint32_t sb, int bm, int bn, int t, int lane, int wm, int wn,
    float d[4][4][4])
{
    const int r0 = t >> 2,         c0 = t & 3;
    const int r1 = (t + 256) >> 2, c1 = t & 3;

    auto load_chunk = [&](int chunk, int st) {
        const size_t kb = (size_t)chunk * 32;
        const uint32_t s = sb + (uint32_t)st * STAGE_B;
        {
            uint32_t so = sw_off(r0, c0);
            const size_t ga = (size_t)(bm + r0) * D_ + kb + c0 * 8;
            const size_t gb = (size_t)(bn + r0) * D_ + kb + c0 * 8;
            CP_ASYNC_16(s + so,         Ahi + ga);
            CP_ASYNC_16(s + 8192  + so, Alo + ga);
            CP_ASYNC_16(s + 16384 + so, Bhi + gb);
            CP_ASYNC_16(s + 24576 + so, Blo + gb);
        }
        {
            uint32_t so = sw_off(r1, c1);
            const size_t ga = (size_t)(bm + r1) * D_ + kb + c1 * 8;
            const size_t gb = (size_t)(bn + r1) * D_ + kb + c1 * 8;
            CP_ASYNC_16(s + so,         Ahi + ga);
            CP_ASYNC_16(s + 8192  + so, Alo + ga);
            CP_ASYNC_16(s + 16384 + so, Bhi + gb);
            CP_ASYNC_16(s + 24576 + so, Blo + gb);
        }
        CP_COMMIT();
    };

    load_chunk(0, 0);
    load_chunk(1, 1);

    for (int chunk = 0; chunk < NCHUNK; chunk++) {
        if (chunk + 2 < NCHUNK) cp_wait<1>();
        else                    cp_wait<0>();
        __syncthreads();
        if (chunk + 2 < NCHUNK) load_chunk(chunk + 2, (chunk + 2) % 3);

        const uint32_t tAh = sb + (uint32_t)(chunk % 3) * STAGE_B;
        const uint32_t tAl = tAh + 8192;
        const uint32_t tBh = tAh + 16384;
        const uint32_t tBl = tAh + 24576;

#pragma unroll
        for (int ks = 0; ks < 2; ks++) {
            uint32_t ah[4][4], al[4][4];
#pragma unroll
            for (int i = 0; i < 4; i++) {
                ldm_a(tAh, wm + i * 16, ks, lane, ah[i]);
                ldm_a(tAl, wm + i * 16, ks, lane, al[i]);
            }
            uint32_t bh[2][4], bl[2][4];
#pragma unroll
            for (int jp = 0; jp < 2; jp++) {
                ldm_b(tBh, wn + jp * 16, ks, lane, bh[jp]);
                ldm_b(tBl, wn + jp * 16, ks, lane, bl[jp]);
            }
#pragma unroll
            for (int i = 0; i < 4; i++)
#pragma unroll
                for (int j = 0; j < 4; j++) {
                    const uint32_t* ph = &bh[j >> 1][(j & 1) * 2];
                    const uint32_t* pl = &bl[j >> 1][(j & 1) * 2];
                    mma16816(d[i][j], ah[i], ph);
                    mma16816(d[i][j], ah[i], pl);
                    mma16816(d[i][j], al[i], ph);
                }
        }
    }
}

// ---------------------------------------------------------------------------
// Fused QKV projection
// ---------------------------------------------------------------------------
__global__ __launch_bounds__(256) void gemm_qkv(
    const __nv_bfloat16* __restrict__ Ahi, const __nv_bfloat16* __restrict__ Alo,
    const __nv_bfloat16* __restrict__ Whi, const __nv_bfloat16* __restrict__ Wlo,
    __nv_bfloat16* __restrict__ Qhi, __nv_bfloat16* __restrict__ Qlo,
    __nv_bfloat16* __restrict__ Khi, __nv_bfloat16* __restrict__ Klo,
    __nv_bfloat16* __restrict__ Vhi, __nv_bfloat16* __restrict__ Vlo)
{
    extern __shared__ __align__(1024) char smem[];
    const uint32_t sb = smem_u32(smem);

    const int t     = threadIdx.x;
    const int lane  = t & 31;
    const int w     = t >> 5;
    const int wm    = (w >> 2) * 64;
    const int wn    = (w & 3) * 32;
    const int which = blockIdx.x >> 3;
    const int bn    = (blockIdx.x & 7) * 128;
    const int bm    = blockIdx.y * 128;

    const __nv_bfloat16* Bhi = Whi + (size_t)which * (D_ * D_);
    const __nv_bfloat16* Blo = Wlo + (size_t)which * (D_ * D_);
    __nv_bfloat16* Chi = (which == 0) ? Qhi : (which == 1) ? Khi : Vhi;
    __nv_bfloat16* Clo = (which == 0) ? Qlo : (which == 1) ? Klo : Vlo;
    const float scale = (which == 0) ? 0.125f : 1.0f;

    float d[4][4][4];
#pragma unroll
    for (int i = 0; i < 4; i++)
#pragma unroll
        for (int j = 0; j < 4; j++)
#pragma unroll
            for (int e = 0; e < 4; e++) d[i][j][e] = 0.0f;

    gemm_mainloop(Ahi, Alo, Bhi, Blo, sb, bm, bn, t, lane, wm, wn, d);

#pragma unroll
    for (int i = 0; i < 4; i++) {
        const int row = bm + wm + i * 16 + (lane >> 2);
#pragma unroll
        for (int j = 0; j < 4; j++) {
            const int col = bn + wn + j * 8 + (lane & 3) * 2;
            uint32_t h01, l01, h23, l23;
            pack_hilo(d[i][j][0] * scale, d[i][j][1] * scale, h01, l01);
            pack_hilo(d[i][j][2] * scale, d[i][j][3] * scale, h23, l23);
            *(uint32_t*)(Chi + (size_t)row * D_ + col)       = h01;
            *(uint32_t*)(Clo + (size_t)row * D_ + col)       = l01;
            *(uint32_t*)(Chi + (size_t)(row + 8) * D_ + col) = h23;
            *(uint32_t*)(Clo + (size_t)(row + 8) * D_ + col) = l23;
        }
    }
}

// ---------------------------------------------------------------------------
// O-projection GEMM (fp32 output)
// ---------------------------------------------------------------------------
__global__ __launch_bounds__(256) void gemm_out(
    const __nv_bfloat16* __restrict__ Ahi, const __nv_bfloat16* __restrict__ Alo,
    const __nv_bfloat16* __restrict__ Bhi, const __nv_bfloat16* __restrict__ Blo,
    float* __restrict__ C)
{
    extern __shared__ __align__(1024) char smem[];
    const uint32_t sb = smem_u32(smem);

    const int t    = threadIdx.x;
    const int lane = t & 31;
    const int w    = t >> 5;
    const int wm   = (w >> 2) * 64;
    const int wn   = (w & 3) * 32;
    const int bm   = blockIdx.y * 128;
    const int bn   = blockIdx.x * 128;

    float d[4][4][4];
#pragma unroll
    for (int i = 0; i < 4; i++)
#pragma unroll
        for (int j = 0; j < 4; j++)
#pragma unroll
            for (int e = 0; e < 4; e++) d[i][j][e] = 0.0f;

    gemm_mainloop(Ahi, Alo, Bhi, Blo, sb, bm, bn, t, lane, wm, wn, d);

#pragma unroll
    for (int i = 0; i < 4; i++) {
        const int row = bm + wm + i * 16 + (lane >> 2);
#pragma unroll
        for (int j = 0; j < 4; j++) {
            const int col = bn + wn + j * 8 + (lane & 3) * 2;
            *(float2*)(C + (size_t)row * D_ + col)       = make_float2(d[i][j][0], d[i][j][1]);
            *(float2*)(C + (size_t)(row + 8) * D_ + col) = make_float2(d[i][j][2], d[i][j][3]);
        }
    }
}

// ---------------------------------------------------------------------------
// Flash attention on mma.sync — R7 q64 version (2 CTAs/SM; validated)
// ---------------------------------------------------------------------------
#define ATT_SMEM 81920

__global__ __launch_bounds__(128) void attn_mma(
    const __nv_bfloat16* __restrict__ Qhi, const __nv_bfloat16* __restrict__ Qlo,
    const __nv_bfloat16* __restrict__ Khi, const __nv_bfloat16* __restrict__ Klo,
    const __nv_bfloat16* __restrict__ Vhi, const __nv_bfloat16* __restrict__ Vlo,
    __nv_bfloat16* __restrict__ AOhi, __nv_bfloat16* __restrict__ AOlo)
{
    extern __shared__ __align__(1024) char smem[];
    const uint32_t sb = smem_u32(smem);
    const int qt   = (int)gridDim.x - 1 - (int)blockIdx.x;
    const int h    = blockIdx.y;
    const int b    = blockIdx.z;
    const int tid  = threadIdx.x;
    const int lane = tid & 31;
    const int w    = tid >> 5;

    const size_t rowbase = (size_t)b * S_;
    const size_t cb      = (size_t)h * DK_;
    const int    q0      = qt * 64;

    const uint32_t sQh = sb, sQl = sb + 8192;

#pragma unroll
    for (int i = 0; i < 4; i++) {
        int p = tid + 128 * i; int r = p >> 3, ck = p & 7;
        size_t g = (rowbase + q0 + r) * D_ + cb + ck * 8;
        uint32_t so = swoff128(r, ck);
        CP_ASYNC_16(sQh + so, Qhi + g);
        CP_ASYNC_16(sQl + so, Qlo + g);
    }
    CP_COMMIT();

    auto load_kv = [&](int kt, int st) {
        uint32_t s = sb + 16384 + (uint32_t)st * 32768;
#pragma unroll
        for (int i = 0; i < 4; i++) {
            int p = tid + 128 * i; int r = p >> 3, ck = p & 7;
            uint32_t so = swoff128(r, ck);
            size_t g = (rowbase + kt * 64 + r) * D_ + cb + ck * 8;
            CP_ASYNC_16(s + so,         Khi + g);
            CP_ASYNC_16(s + 8192  + so, Klo + g);
            CP_ASYNC_16(s + 16384 + so, Vhi + g);
            CP_ASYNC_16(s + 24576 + so, Vlo + g);
        }
        CP_COMMIT();
    };
    load_kv(0, 0);

    cp_wait<1>();
    __syncthreads();

    uint32_t qh[4][4], ql[4][4];
#pragma unroll
    for (int t4 = 0; t4 < 4; t4++) {
        ldm_a128(sQh, w * 16, t4, lane, qh[t4]);
        ldm_a128(sQl, w * 16, t4, lane, ql[t4]);
    }

    float o[8][4];
#pragma unroll
    for (int j = 0; j < 8; j++)
#pragma unroll
        for (int e = 0; e < 4; e++) o[j][e] = 0.0f;
    float miA = -INFINITY, miB = -INFINITY, liA = 0.0f, liB = 0.0f;

    const int rA = w * 16 + (lane >> 2);
    const int cl = 2 * (lane & 3);

    for (int kt = 0; kt <= qt; kt++) {
        const int st = kt & 1;
        if (kt < qt) { load_kv(kt + 1, st ^ 1); cp_wait<1>(); }
        else         { cp_wait<0>(); }
        __syncthreads();

        const uint32_t Kh = sb + 16384 + (uint32_t)st * 32768;
        const uint32_t Kl = Kh + 8192, Vh = Kh + 16384, Vl = Kh + 24576;

        float s[8][4];
#pragma unroll
        for (int j = 0; j < 8; j++)
#pragma unroll
            for (int e = 0; e < 4; e++) s[j][e] = 0.0f;

#pragma unroll
        for (int t4 = 0; t4 < 4; t4++) {
#pragma unroll
            for (int jp = 0; jp < 4; jp++) {
                uint32_t kh[4], kl[4];
                ldm_b128(Kh, jp * 16, t4, lane, kh);
                ldm_b128(Kl, jp * 16, t4, lane, kl);
                mma16816(s[2 * jp],     qh[t4], kh);
                mma16816(s[2 * jp],     qh[t4], kl);
                mma16816(s[2 * jp],     ql[t4], kh);
                mma16816(s[2 * jp + 1], qh[t4], kh + 2);
                mma16816(s[2 * jp + 1], qh[t4], kl + 2);
                mma16816(s[2 * jp + 1], ql[t4], kh + 2);
            }
        }

        if (kt == qt) {
#pragma unroll
            for (int j = 0; j < 8; j++) {
                int c = 8 * j + cl;
                if (c     > rA)     s[j][0] = -INFINITY;
                if (c + 1 > rA)     s[j][1] = -INFINITY;
                if (c     > rA + 8) s[j][2] = -INFINITY;
                if (c + 1 > rA + 8) s[j][3] = -INFINITY;
            }
        }

        float mxA = s[0][0], mxB = s[0][2];
#pragma unroll
        for (int j = 0; j < 8; j++) {
            mxA = fmaxf(mxA, fmaxf(s[j][0], s[j][1]));
            mxB = fmaxf(mxB, fmaxf(s[j][2], s[j][3]));
        }
        mxA = fmaxf(mxA, __shfl_xor_sync(0xffffffffu, mxA, 1));
        mxA = fmaxf(mxA, __shfl_xor_sync(0xffffffffu, mxA, 2));
        mxB = fmaxf(mxB, __shfl_xor_sync(0xffffffffu, mxB, 1));
        mxB = fmaxf(mxB, __shfl_xor_sync(0xffffffffu, mxB, 2));

        float nA = fmaxf(miA, mxA), nB = fmaxf(miB, mxB);
        float aA = __expf(miA - nA), aB = __expf(miB - nB);
        miA = nA; miB = nB;
        liA *= aA; liB *= aB;
#pragma unroll
        for (int j = 0; j < 8; j++) {
            s[j][0] = __expf(s[j][0] - miA);
            s[j][1] = __expf(s[j][1] - miA);
            s[j][2] = __expf(s[j][2] - miB);
            s[j][3] = __expf(s[j][3] - miB);
            liA += s[j][0] + s[j][1];
            liB += s[j][2] + s[j][3];
            o[j][0] *= aA; o[j][1] *= aA; o[j][2] *= aB; o[j][3] *= aB;
        }

        uint32_t ph[4][4], pl[4][4];
#pragma unroll
        for (int t4 = 0; t4 < 4; t4++) {
            pack_hilo(s[2 * t4][0],     s[2 * t4][1],     ph[t4][0], pl[t4][0]);
            pack_hilo(s[2 * t4][2],     s[2 * t4][3],     ph[t4][1], pl[t4][1]);
            pack_hilo(s[2 * t4 + 1][0], s[2 * t4 + 1][1], ph[t4][2], pl[t4][2]);
            pack_hilo(s[2 * t4 + 1][2], s[2 * t4 + 1][3], ph[t4][3], pl[t4][3]);
        }

#pragma unroll
        for (int t4 = 0; t4 < 4; t4++) {
#pragma unroll
            for (int jp = 0; jp < 4; jp++) {
                uint32_t vh[4], vl[4];
                ldm_vt128(Vh, t4 * 16, jp, lane, vh);
                ldm_vt128(Vl, t4 * 16, jp, lane, vl);
                mma16816(o[2 * jp],     ph[t4], vh);
                mma16816(o[2 * jp],     pl[t4], vh);
                mma16816(o[2 * jp],     ph[t4], vl);
                mma16816(o[2 * jp + 1], ph[t4], vh + 2);
                mma16816(o[2 * jp + 1], pl[t4], vh + 2);
                mma16816(o[2 * jp + 1], ph[t4], vl + 2);
            }
        }
        __syncthreads();
    }

    liA += __shfl_xor_sync(0xffffffffu, liA, 1);
    liA += __shfl_xor_sync(0xffffffffu, liA, 2);
    liB += __shfl_xor_sync(0xffffffffu, liB, 1);
    liB += __shfl_xor_sync(0xffffffffu, liB, 2);
    const float invA = 1.0f / liA, invB = 1.0f / liB;

    const size_t gA = (rowbase + q0 + rA) * D_ + cb + cl;
#pragma unroll
    for (int j = 0; j < 8; j++) {
        uint32_t hA, lA, hB, lB;
        pack_hilo(o[j][0] * invA, o[j][1] * invA, hA, lA);
        pack_hilo(o[j][2] * invB, o[j][3] * invB, hB, lB);
        *(uint32_t*)(AOhi + gA + 8 * j)           = hA;
        *(uint32_t*)(AOlo + gA + 8 * j)           = lA;
        *(uint32_t*)(AOhi + gA + 8 * j + 8 * D_)  = hB;
        *(uint32_t*)(AOlo + gA + 8 * j + 8 * D_)  = lB;
    }
}

// ---------------------------------------------------------------------------
// kernel_launch
// ---------------------------------------------------------------------------
extern "C" void kernel_launch(void* const* d_in, const int* in_sizes, int n_in,
                              void* d_out, int out_size)
{
    const float* x  = (const float*)d_in[0];
    const float* wp[4] = { (const float*)d_in[1], (const float*)d_in[2],
                           (const float*)d_in[3], (const float*)d_in[4] };
    float* out = (float*)d_out;

    __nv_bfloat16 *xhi, *xlo, *qhi, *qlo, *khi, *klo, *vhi, *vlo, *aohi, *aolo, *whi, *wlo;
    cudaGetSymbolAddress((void**)&xhi,  g_xhi);
    cudaGetSymbolAddress((void**)&xlo,  g_xlo);
    cudaGetSymbolAddress((void**)&qhi,  g_qhi);
    cudaGetSymbolAddress((void**)&qlo,  g_qlo);
    cudaGetSymbolAddress((void**)&khi,  g_khi);
    cudaGetSymbolAddress((void**)&klo,  g_klo);
    cudaGetSymbolAddress((void**)&vhi,  g_vhi);
    cudaGetSymbolAddress((void**)&vlo,  g_vlo);
    cudaGetSymbolAddress((void**)&aohi, g_aohi);
    cudaGetSymbolAddress((void**)&aolo, g_aolo);
    cudaGetSymbolAddress((void**)&whi,  g_whi);
    cudaGetSymbolAddress((void**)&wlo,  g_wlo);

    const int n2x = M_ * D_ / 2;
    const int n2w = D_ * D_ / 2;
    f32_to_hilo<<<(n2x + 255) / 256, 256>>>(x, xhi, xlo, n2x);
    w4_to_hilo<<<dim3((n2w + 255) / 256, 4), 256>>>(wp[0], wp[1], wp[2], wp[3], whi, wlo);

    cudaFuncSetAttribute(gemm_qkv, cudaFuncAttributeMaxDynamicSharedMemorySize, GEMM_SMEM);
    cudaFuncSetAttribute(gemm_out, cudaFuncAttributeMaxDynamicSharedMemorySize, GEMM_SMEM);
    cudaFuncSetAttribute(attn_mma, cudaFuncAttributeMaxDynamicSharedMemorySize, ATT_SMEM);

    gemm_qkv<<<dim3(24, M_ / 128), 256, GEMM_SMEM>>>(xhi, xlo, whi, wlo,
                                                     qhi, qlo, khi, klo, vhi, vlo);

    attn_mma<<<dim3(S_ / 64, H_, B_), 128, ATT_SMEM>>>(qhi, qlo, khi, klo, vhi, vlo, aohi, aolo);

    gemm_out<<<dim3(D_ / 128, M_ / 128), 256, GEMM_SMEM>>>(
        aohi, aolo, whi + 3 * (size_t)(D_ * D_), wlo + 3 * (size_t)(D_ * D_), out);
}